// round 4
// baseline (speedup 1.0000x reference)
#include <cuda_runtime.h>
#include <cstdint>

#define T_STEPS 1000
#define BATCH   8192
#define IN      9
#define HID     96
#define OUTD    3
#define HS      12
#define GRP     8
#define HP      6

typedef unsigned long long u64;

union f2u {
    u64 u;
    float f[2];
};

__device__ __forceinline__ u64 pack2(float lo, float hi) {
    f2u v; v.f[0] = lo; v.f[1] = hi; return v.u;
}
__device__ __forceinline__ u64 ffma2(u64 a, u64 b, u64 c) {
    u64 d;
    asm("fma.rn.f32x2 %0, %1, %2, %3;" : "=l"(d) : "l"(a), "l"(b), "l"(c));
    return d;
}
__device__ __forceinline__ u64 add2(u64 a, u64 b) {
    u64 d;
    asm("add.rn.f32x2 %0, %1, %2;" : "=l"(d) : "l"(a), "l"(b));
    return d;
}
__device__ __forceinline__ u64 mul2(u64 a, u64 b) {
    u64 d;
    asm("mul.rn.f32x2 %0, %1, %2;" : "=l"(d) : "l"(a), "l"(b));
    return d;
}
// spike = (m > 1) ? 1 : 0 per half, branch/pred-free
__device__ __forceinline__ u64 spike2(u64 m) {
    const u64 NEG12 = 0xBF800000BF800000ull;   // {-1, -1}
    const u64 BIG2  = 0x7149F2CA7149F2CAull;   // {1e30, 1e30}
    f2u p; p.u = mul2(add2(m, NEG12), BIG2);
    f2u s;
    s.f[0] = fminf(fmaxf(p.f[0], 0.0f), 1.0f);
    s.f[1] = fminf(fmaxf(p.f[1], 0.0f), 1.0f);
    return s.u;
}

// One layer-1 step: membrane update, arithmetic spike, layer-2 partials.
__device__ __forceinline__ void l1_step(const u64 (&xd)[IN],
                                        u64 (&mp)[HP], u64 (&sp)[HP],
                                        const u64 (&w1p)[IN][HP],
                                        const u64 (&b1p)[HP],
                                        const u64 (&w2p)[OUTD][HP],
                                        float& o0, float& o1, float& o2)
{
    const u64 BETA2 = 0x3F6B851F3F6B851Full;   // {0.92f, 0.92f}
    const u64 NEG12 = 0xBF800000BF800000ull;   // {-1, -1}

#pragma unroll
    for (int j = 0; j < HP; j++) {
        u64 m = ffma2(BETA2, mp[j], b1p[j]);
        m = ffma2(sp[j], NEG12, m);
#pragma unroll
        for (int i = 0; i < IN; i++)
            m = ffma2(xd[i], w1p[i][j], m);
        mp[j] = m;
    }

    u64 c0 = 0ull, c1 = 0ull, c2 = 0ull;
#pragma unroll
    for (int j = 0; j < HP; j++) {
        const u64 s = spike2(mp[j]);
        sp[j] = s;
        c0 = ffma2(s, w2p[0][j], c0);
        c1 = ffma2(s, w2p[1][j], c1);
        c2 = ffma2(s, w2p[2][j], c2);
    }
    f2u a0, a1, a2;
    a0.u = c0; a1.u = c1; a2.u = c2;
    o0 = a0.f[0] + a0.f[1];
    o1 = a1.f[0] + a1.f[1];
    o2 = a2.f[0] + a2.f[1];
}

__global__ __launch_bounds__(128)
void snn_kernel(const float* __restrict__ X,
                const float* __restrict__ W1,
                const float* __restrict__ B1,
                const float* __restrict__ W2,
                const float* __restrict__ B2,
                float* __restrict__ out)
{
    const int tid  = blockIdx.x * blockDim.x + threadIdx.x;
    const int b    = tid >> 3;
    const int pos  = tid & 7;
    const int hbase = pos * HS;

    // ---- Weights to registers ----
    u64 w1p[IN][HP];
#pragma unroll
    for (int j = 0; j < HP; j++) {
        const int h0 = hbase + 2 * j;
#pragma unroll
        for (int i = 0; i < IN; i++)
            w1p[i][j] = pack2(W1[h0 * IN + i], W1[(h0 + 1) * IN + i]);
    }
    u64 b1p[HP];
#pragma unroll
    for (int j = 0; j < HP; j++)
        b1p[j] = pack2(B1[hbase + 2 * j], B1[hbase + 2 * j + 1]);

    u64 w2p[OUTD][HP];
#pragma unroll
    for (int o = 0; o < OUTD; o++)
#pragma unroll
        for (int j = 0; j < HP; j++)
            w2p[o][j] = pack2(W2[o * HID + hbase + 2 * j],
                              W2[o * HID + hbase + 2 * j + 1]);

    const float b2r0 = B2[0], b2r1 = B2[1], b2r2 = B2[2];

    // ---- State ----
    u64 mp[HP], sp[HP];
#pragma unroll
    for (int j = 0; j < HP; j++) { mp[j] = 0ull; sp[j] = 0ull; }
    float m20 = 0.f, m21 = 0.f, m22 = 0.f;
    float s20 = 0.f, s21 = 0.f, s22 = 0.f;

    const float* xptr = X + (size_t)b * IN;
    const size_t xstride = (size_t)BATCH * IN;
    const size_t orow = (size_t)BATCH * OUTD;       // 24576
    const size_t memoff = (size_t)T_STEPS * orow;

    // per-lane store pointer (lanes 0-2: spk2, lanes 3-5: mem2, 6-7 idle)
    float* stp = out + (size_t)b * OUTD
               + (size_t)((pos < 3) ? pos : pos - 3)
               + ((pos < 3) ? 0 : memoff);

    // ---- Pipeline prologue: step 0 ----
    float nx[IN];
#pragma unroll
    for (int i = 0; i < IN; i++) nx[i] = __ldg(xptr + i);

    u64 xd[IN];
#pragma unroll
    for (int i = 0; i < IN; i++) xd[i] = pack2(nx[i], nx[i]);
#pragma unroll
    for (int i = 0; i < IN; i++) nx[i] = __ldg(xptr + xstride + i);

    float cp0, cp1, cp2;
    l1_step(xd, mp, sp, w1p, b1p, w2p, cp0, cp1, cp2);

    // ---- Main loop: compute layer1(t), finalize step t-1 ----
#pragma unroll 1
    for (int t = 1; t < T_STEPS; t++) {
        // start reduction of previous step's partials (overlaps layer1 below)
        float r0 = cp0, r1 = cp1, r2 = cp2;
        r0 += __shfl_xor_sync(0xffffffffu, r0, 1);
        r1 += __shfl_xor_sync(0xffffffffu, r1, 1);
        r2 += __shfl_xor_sync(0xffffffffu, r2, 1);
        r0 += __shfl_xor_sync(0xffffffffu, r0, 2);
        r1 += __shfl_xor_sync(0xffffffffu, r1, 2);
        r2 += __shfl_xor_sync(0xffffffffu, r2, 2);
        r0 += __shfl_xor_sync(0xffffffffu, r0, 4);
        r1 += __shfl_xor_sync(0xffffffffu, r1, 4);
        r2 += __shfl_xor_sync(0xffffffffu, r2, 4);

        // layer1 for step t (uses x_t already in nx)
#pragma unroll
        for (int i = 0; i < IN; i++) xd[i] = pack2(nx[i], nx[i]);
        if (t + 1 < T_STEPS) {
            const float* nxt = xptr + (size_t)(t + 1) * xstride;
#pragma unroll
            for (int i = 0; i < IN; i++) nx[i] = __ldg(nxt + i);
        }
        float np0, np1, np2;
        l1_step(xd, mp, sp, w1p, b1p, w2p, np0, np1, np2);

        // finalize step t-1: mem2 update + store
        m20 = fmaf(0.92f, m20, r0 + b2r0) - s20;
        m21 = fmaf(0.92f, m21, r1 + b2r1) - s21;
        m22 = fmaf(0.92f, m22, r2 + b2r2) - s22;
        s20 = fminf(fmaxf((m20 - 1.0f) * 1e30f, 0.0f), 1.0f);
        s21 = fminf(fmaxf((m21 - 1.0f) * 1e30f, 0.0f), 1.0f);
        s22 = fminf(fmaxf((m22 - 1.0f) * 1e30f, 0.0f), 1.0f);

        float val = s20;
        val = (pos == 1) ? s21 : val;
        val = (pos == 2) ? s22 : val;
        val = (pos == 3) ? m20 : val;
        val = (pos == 4) ? m21 : val;
        val = (pos == 5) ? m22 : val;
        if (pos < 6) *stp = val;
        stp += orow;

        cp0 = np0; cp1 = np1; cp2 = np2;
    }

    // ---- Drain: finalize step T-1 ----
    {
        float r0 = cp0, r1 = cp1, r2 = cp2;
        r0 += __shfl_xor_sync(0xffffffffu, r0, 1);
        r1 += __shfl_xor_sync(0xffffffffu, r1, 1);
        r2 += __shfl_xor_sync(0xffffffffu, r2, 1);
        r0 += __shfl_xor_sync(0xffffffffu, r0, 2);
        r1 += __shfl_xor_sync(0xffffffffu, r1, 2);
        r2 += __shfl_xor_sync(0xffffffffu, r2, 2);
        r0 += __shfl_xor_sync(0xffffffffu, r0, 4);
        r1 += __shfl_xor_sync(0xffffffffu, r1, 4);
        r2 += __shfl_xor_sync(0xffffffffu, r2, 4);

        m20 = fmaf(0.92f, m20, r0 + b2r0) - s20;
        m21 = fmaf(0.92f, m21, r1 + b2r1) - s21;
        m22 = fmaf(0.92f, m22, r2 + b2r2) - s22;
        s20 = fminf(fmaxf((m20 - 1.0f) * 1e30f, 0.0f), 1.0f);
        s21 = fminf(fmaxf((m21 - 1.0f) * 1e30f, 0.0f), 1.0f);
        s22 = fminf(fmaxf((m22 - 1.0f) * 1e30f, 0.0f), 1.0f);

        float val = s20;
        val = (pos == 1) ? s21 : val;
        val = (pos == 2) ? s22 : val;
        val = (pos == 3) ? m20 : val;
        val = (pos == 4) ? m21 : val;
        val = (pos == 5) ? m22 : val;
        if (pos < 6) *stp = val;
    }
}

extern "C" void kernel_launch(void* const* d_in, const int* in_sizes, int n_in,
                              void* d_out, int out_size)
{
    const float* X  = (const float*)d_in[0];
    const float* W1 = (const float*)d_in[1];
    const float* B1 = (const float*)d_in[2];
    const float* W2 = (const float*)d_in[3];
    const float* B2 = (const float*)d_in[4];
    float* out = (float*)d_out;

    const int threads = 128;
    const int blocks  = (BATCH * GRP) / threads;  // 512
    snn_kernel<<<blocks, threads>>>(X, W1, B1, W2, B2, out);
}

// round 5
// speedup vs baseline: 1.1520x; 1.1520x over previous
#include <cuda_runtime.h>
#include <cstdint>

#define T_STEPS 1000
#define BATCH   8192
#define IN      9
#define HID     96
#define OUTD    3
#define HS      6    // hidden units per thread
#define GRP     16   // threads per batch element
#define HP      3    // f32x2 pairs per thread

typedef unsigned long long u64;

union f2u {
    u64 u;
    float f[2];
};

__device__ __forceinline__ u64 pack2(float lo, float hi) {
    f2u v; v.f[0] = lo; v.f[1] = hi; return v.u;
}
__device__ __forceinline__ u64 ffma2(u64 a, u64 b, u64 c) {
    u64 d;
    asm("fma.rn.f32x2 %0, %1, %2, %3;" : "=l"(d) : "l"(a), "l"(b), "l"(c));
    return d;
}
__device__ __forceinline__ u64 add2(u64 a, u64 b) {
    u64 d;
    asm("add.rn.f32x2 %0, %1, %2;" : "=l"(d) : "l"(a), "l"(b));
    return d;
}
__device__ __forceinline__ u64 mul2(u64 a, u64 b) {
    u64 d;
    asm("mul.rn.f32x2 %0, %1, %2;" : "=l"(d) : "l"(a), "l"(b));
    return d;
}
// spike = (m > 1) ? 1 : 0 per packed half, branch/pred-free
__device__ __forceinline__ u64 spike2(u64 m) {
    const u64 NEG12 = 0xBF800000BF800000ull;   // {-1, -1}
    const u64 BIG2  = 0x7149F2CA7149F2CAull;   // {1e30, 1e30}
    f2u p; p.u = mul2(add2(m, NEG12), BIG2);
    f2u s;
    s.f[0] = fminf(fmaxf(p.f[0], 0.0f), 1.0f);
    s.f[1] = fminf(fmaxf(p.f[1], 0.0f), 1.0f);
    return s.u;
}

__global__ __launch_bounds__(128, 4)
void snn_kernel(const float* __restrict__ X,
                const float* __restrict__ W1,
                const float* __restrict__ B1,
                const float* __restrict__ W2,
                const float* __restrict__ B2,
                float* __restrict__ out)
{
    const int tid  = blockIdx.x * 128 + threadIdx.x;
    const int b    = tid >> 4;       // batch element
    const int pos  = tid & 15;       // lane within 16-thread group
    const int hbase = pos * HS;

    // ---- Weight slices to registers (once): 78 regs total ----
    u64 w1p[IN][HP];
#pragma unroll
    for (int j = 0; j < HP; j++) {
        const int h0 = hbase + 2 * j;
#pragma unroll
        for (int i = 0; i < IN; i++)
            w1p[i][j] = pack2(W1[h0 * IN + i], W1[(h0 + 1) * IN + i]);
    }
    u64 b1p[HP];
#pragma unroll
    for (int j = 0; j < HP; j++)
        b1p[j] = pack2(B1[hbase + 2 * j], B1[hbase + 2 * j + 1]);

    u64 w2p[OUTD][HP];
#pragma unroll
    for (int o = 0; o < OUTD; o++)
#pragma unroll
        for (int j = 0; j < HP; j++)
            w2p[o][j] = pack2(W2[o * HID + hbase + 2 * j],
                              W2[o * HID + hbase + 2 * j + 1]);

    const float b2r0 = B2[0], b2r1 = B2[1], b2r2 = B2[2];

    const u64 BETA2 = 0x3F6B851F3F6B851Full;   // {0.92, 0.92}
    const u64 NEG12 = 0xBF800000BF800000ull;   // {-1, -1}

    // ---- State ----
    u64 mp[HP], sp[HP];
#pragma unroll
    for (int j = 0; j < HP; j++) { mp[j] = 0ull; sp[j] = 0ull; }
    float m20 = 0.f, m21 = 0.f, m22 = 0.f;
    float s20 = 0.f, s21 = 0.f, s22 = 0.f;

    const float* xptr = X + b * IN;          // 32-bit offsets throughout
    const int xstride = BATCH * IN;          // 73728
    const int orow    = BATCH * OUTD;        // 24576
    const int memoff  = T_STEPS * orow;

    // per-lane store pointer (lanes 0-2: spk2, lanes 3-5: mem2, rest idle)
    float* stp = out + b * OUTD
               + ((pos < 3) ? pos : pos - 3)
               + ((pos < 3) ? 0 : memoff);

    // prefetch x for t=0
    float nx[IN];
#pragma unroll
    for (int i = 0; i < IN; i++) nx[i] = __ldg(xptr + i);

#pragma unroll 1
    for (int t = 0; t < T_STEPS; t++) {
        // decay + reset (uses prev spikes)
#pragma unroll
        for (int j = 0; j < HP; j++) {
            u64 m = ffma2(BETA2, mp[j], b1p[j]);
            mp[j] = ffma2(sp[j], NEG12, m);
        }
        // x @ W1 slice, i-outer so only one packed-x is live at a time
#pragma unroll
        for (int i = 0; i < IN; i++) {
            const u64 xd = pack2(nx[i], nx[i]);
#pragma unroll
            for (int j = 0; j < HP; j++)
                mp[j] = ffma2(xd, w1p[i][j], mp[j]);
        }

        // prefetch next timestep's x (overlaps everything below)
        if (t + 1 < T_STEPS) {
            const float* nxt = xptr + (t + 1) * xstride;
#pragma unroll
            for (int i = 0; i < IN; i++) nx[i] = __ldg(nxt + i);
        }

        // spikes + layer-2 partials
        u64 c0 = 0ull, c1 = 0ull, c2 = 0ull;
#pragma unroll
        for (int j = 0; j < HP; j++) {
            const u64 s = spike2(mp[j]);
            sp[j] = s;
            c0 = ffma2(s, w2p[0][j], c0);
            c1 = ffma2(s, w2p[1][j], c1);
            c2 = ffma2(s, w2p[2][j], c2);
        }
        f2u a0, a1, a2;
        a0.u = c0; a1.u = c1; a2.u = c2;
        float r0 = a0.f[0] + a0.f[1];
        float r1 = a1.f[0] + a1.f[1];
        float r2 = a2.f[0] + a2.f[1];

        // reduce across the 16-lane group
        r0 += __shfl_xor_sync(0xffffffffu, r0, 1);
        r1 += __shfl_xor_sync(0xffffffffu, r1, 1);
        r2 += __shfl_xor_sync(0xffffffffu, r2, 1);
        r0 += __shfl_xor_sync(0xffffffffu, r0, 2);
        r1 += __shfl_xor_sync(0xffffffffu, r1, 2);
        r2 += __shfl_xor_sync(0xffffffffu, r2, 2);
        r0 += __shfl_xor_sync(0xffffffffu, r0, 4);
        r1 += __shfl_xor_sync(0xffffffffu, r1, 4);
        r2 += __shfl_xor_sync(0xffffffffu, r2, 4);
        r0 += __shfl_xor_sync(0xffffffffu, r0, 8);
        r1 += __shfl_xor_sync(0xffffffffu, r1, 8);
        r2 += __shfl_xor_sync(0xffffffffu, r2, 8);

        // mem2 update (replicated in all 16 lanes; rst2 == prev spk2)
        m20 = fmaf(0.92f, m20, r0 + b2r0) - s20;
        m21 = fmaf(0.92f, m21, r1 + b2r1) - s21;
        m22 = fmaf(0.92f, m22, r2 + b2r2) - s22;
        s20 = fminf(fmaxf((m20 - 1.0f) * 1e30f, 0.0f), 1.0f);
        s21 = fminf(fmaxf((m21 - 1.0f) * 1e30f, 0.0f), 1.0f);
        s22 = fminf(fmaxf((m22 - 1.0f) * 1e30f, 0.0f), 1.0f);

        // distributed store
        float val = s20;
        val = (pos == 1) ? s21 : val;
        val = (pos == 2) ? s22 : val;
        val = (pos == 3) ? m20 : val;
        val = (pos == 4) ? m21 : val;
        val = (pos == 5) ? m22 : val;
        if (pos < 6) *stp = val;
        stp += orow;
    }
}

extern "C" void kernel_launch(void* const* d_in, const int* in_sizes, int n_in,
                              void* d_out, int out_size)
{
    const float* X  = (const float*)d_in[0];
    const float* W1 = (const float*)d_in[1];
    const float* B1 = (const float*)d_in[2];
    const float* W2 = (const float*)d_in[3];
    const float* B2 = (const float*)d_in[4];
    float* out = (float*)d_out;

    const int threads = 128;
    const int blocks  = (BATCH * GRP) / threads;  // 1024
    snn_kernel<<<blocks, threads>>>(X, W1, B1, W2, B2, out);
}